// round 13
// baseline (speedup 1.0000x reference)
#include <cuda_runtime.h>
#include <cuda_fp16.h>
#include <mma.h>

using namespace nvcuda;

// Problem constants
#define B_  2
#define T_  4096
#define H_  8
#define D_  64
#define C_  64
#define NC_ (T_/C_)            // 64
#define BH_ (B_*H_)            // 16
#define ROWSTRIDE 512          // H_*D_
#define SB_ 72                 // fp16 smem row stride (LDSM conflict-free)
#define HB_ (C_ * SB_)         // 4608 halves = 9216 bytes per buffer

#define NTILE_ ((size_t)BH_ * NC_)        // 1024 tiles
#define TILEELEMS_ (D_ * D_)              // 4096

// Scratch: fp32 chunk sums, fp16 prefix state, fp16 quantized K/V planes.
__device__ float  g_Sf [NTILE_ * TILEELEMS_];   // 16MB
__device__ __half g_M  [NTILE_ * TILEELEMS_];   // 8MB
__device__ __half g_K16[NTILE_ * TILEELEMS_];   // 8MB
__device__ __half g_V16[NTILE_ * TILEELEMS_];   // 8MB

typedef wmma::fragment<wmma::matrix_a, 16, 16, 16, __half, wmma::row_major> FragAR;
typedef wmma::fragment<wmma::matrix_a, 16, 16, 16, __half, wmma::col_major> FragAC;
typedef wmma::fragment<wmma::matrix_b, 16, 16, 16, __half, wmma::row_major> FragBR;
typedef wmma::fragment<wmma::matrix_b, 16, 16, 16, __half, wmma::col_major> FragBC;
typedef wmma::fragment<wmma::accumulator, 16, 16, 16, float> FragAcc;

// Quantize 4 fp32 to fp16; store to smem AND gmem (same registers).
__device__ __forceinline__ void quant_store4_dual(__half* Bq, int sidx,
                                                  __half* Gq, int gidx, float4 x) {
    __half2 h01 = __floats2half2_rn(x.x, x.y);
    __half2 h23 = __floats2half2_rn(x.z, x.w);
    uint2 hh;
    hh.x = *(unsigned*)&h01; hh.y = *(unsigned*)&h23;
    *(uint2*)&Bq[sidx] = hh;
    *(uint2*)&Gq[gidx] = hh;
}

__device__ __forceinline__ void quant_store4(__half* Bq, int idx, float4 x) {
    __half2 h01 = __floats2half2_rn(x.x, x.y);
    __half2 h23 = __floats2half2_rn(x.z, x.w);
    uint2 hh;
    hh.x = *(unsigned*)&h01; hh.y = *(unsigned*)&h23;
    *(uint2*)&Bq[idx] = hh;
}

__device__ __forceinline__ void cp_async16(void* sdst, const void* gsrc) {
    unsigned s = (unsigned)__cvta_generic_to_shared(sdst);
    asm volatile("cp.async.cg.shared.global [%0], [%1], 16;" :: "r"(s), "l"(gsrc));
}
__device__ __forceinline__ void cp_commit() { asm volatile("cp.async.commit_group;"); }
__device__ __forceinline__ void cp_wait0()  { asm volatile("cp.async.wait_group 0;" ::: "memory"); }

// ---------------------------------------------------------------------------
// Pass 1: S[d][e] = sum_s V[s][d] * K[s][e] per (bh, chunk).
// Quantized K16/V16 exported to gmem for pass 3. S stored fp32 directly
// (no smem pack tail). Recipe: fill -> sync -> 16 mma -> STG.
// ---------------------------------------------------------------------------
#define SMEM1_BYTES (2 * HB_ * 2)   // 18432

__global__ void __launch_bounds__(128) chunk_sum_kernel(const float* __restrict__ k,
                                                        const float* __restrict__ v) {
    extern __shared__ __align__(16) char smraw1[];
    __half* K16 = (__half*)smraw1;
    __half* V16 = K16 + HB_;

    int blk = blockIdx.x;             // [0, 1024)
    int bh  = blk >> 6;
    int c   = blk & (NC_ - 1);
    int b   = bh >> 3, h = bh & 7;
    int tid = threadIdx.x;

    const float* kbase = k + (((size_t)b * T_ + (size_t)c * C_) * H_ + h) * D_;
    const float* vbase = v + (((size_t)b * T_ + (size_t)c * C_) * H_ + h) * D_;
    __half* gK = g_K16 + (size_t)blk * TILEELEMS_;
    __half* gV = g_V16 + (size_t)blk * TILEELEMS_;

    #pragma unroll
    for (int f = tid; f < C_ * D_ / 4; f += 128) {
        int s = f >> 4;
        int cc = (f & 15) * 4;
        quant_store4_dual(K16, s * SB_ + cc, gK, f * 4,
                          *(const float4*)(kbase + (size_t)s * ROWSTRIDE + cc));
        quant_store4_dual(V16, s * SB_ + cc, gV, f * 4,
                          *(const float4*)(vbase + (size_t)s * ROWSTRIDE + cc));
    }
    __syncthreads();

    int wid = tid >> 5;
    int d0 = wid * 16;

    FragAcc acc[4];
    #pragma unroll
    for (int j = 0; j < 4; j++) wmma::fill_fragment(acc[j], 0.f);

    #pragma unroll
    for (int kk = 0; kk < 4; kk++) {
        int s0 = kk * 16;
        FragAC av;
        wmma::load_matrix_sync(av, &V16[s0 * SB_ + d0], SB_);    // A(d,s)=V[s][d]
        #pragma unroll
        for (int j = 0; j < 4; j++) {
            FragBR bq;
            wmma::load_matrix_sync(bq, &K16[s0 * SB_ + j * 16], SB_); // B(s,e)=K[s][e]
            wmma::mma_sync(acc[j], av, bq, acc[j]);
        }
    }

    // Direct fp32 store to the global S plane (no smem roundtrip)
    float* Sout = g_Sf + (size_t)blk * TILEELEMS_;
    #pragma unroll
    for (int j = 0; j < 4; j++)
        wmma::store_matrix_sync(&Sout[d0 * D_ + j * 16], acc[j], D_, wmma::mem_row_major);
}

// ---------------------------------------------------------------------------
// Pass 2: exclusive prefix over the chunk axis; fp32 in (S), fp16 out (M).
// ---------------------------------------------------------------------------
__global__ void __launch_bounds__(256) prefix_kernel() {
    int gidx = blockIdx.x * 256 + threadIdx.x;   // [0, BH_*4096)
    int bh   = gidx >> 12;
    int idx  = gidx & 4095;
    const float* src = g_Sf + (size_t)bh * NC_ * 4096 + idx;
    __half*      dst = g_M  + (size_t)bh * NC_ * 4096 + idx;

    float vals[NC_];
    #pragma unroll
    for (int c = 0; c < NC_; c++) vals[c] = src[(size_t)c * 4096];
    float run = 0.f;
    #pragma unroll
    for (int c = 0; c < NC_; c++) {
        dst[(size_t)c * 4096] = __float2half_rn(run);
        run += vals[c];
    }
}

// ---------------------------------------------------------------------------
// Pass 3: Y = tril(Q K^T) V + Q M_prev^T per (bh, chunk).
// K/V/M arrive as fp16 via one cp.async volley; only Q is LDG+quantized
// (overlapping the volley). Scores in Sraw (18KB), Shi aliases after mask.
// smem 55.3KB -> 4 CTAs/SM.
// ---------------------------------------------------------------------------
#define SMEM3_BYTES (4 * HB_ * 2 + HB_ * 4)   // 36864 + 18432 = 55296

__global__ void __launch_bounds__(128) output_kernel(const float* __restrict__ q,
                                                     float* __restrict__ y) {
    extern __shared__ __align__(16) char smraw[];
    __half* Q16 = (__half*)smraw;
    __half* K16 = Q16 + HB_;
    __half* V16 = K16 + HB_;
    __half* M16 = V16 + HB_;
    float*  Sraw = (float*)(M16 + HB_);   // fp32 [64][72] (18432B)
    __half* Shi  = (__half*)Sraw;         // aliases first 9216B after mask

    int blk = blockIdx.x;             // [0, 1024)
    int bh  = blk >> 6;
    int c   = blk & (NC_ - 1);
    int b   = bh >> 3, h = bh & 7;
    int tid = threadIdx.x;

    const float* qbase = q + (((size_t)b * T_ + (size_t)c * C_) * H_ + h) * D_;
    const __half* gK = g_K16 + (size_t)blk * TILEELEMS_;
    const __half* gV = g_V16 + (size_t)blk * TILEELEMS_;
    const __half* gM = g_M   + (size_t)blk * TILEELEMS_;

    // One cp.async volley: K, V, M fp16 tiles (gmem rows 64h -> smem rows 72h)
    #pragma unroll
    for (int f = tid; f < D_ * D_ / 8; f += 128) {
        int d = f >> 3;
        int c8 = (f & 7) * 8;
        cp_async16(&K16[d * SB_ + c8], gK + d * D_ + c8);
        cp_async16(&V16[d * SB_ + c8], gV + d * D_ + c8);
        cp_async16(&M16[d * SB_ + c8], gM + d * D_ + c8);
    }
    cp_commit();

    // Q: LDG fp32 + quantize (overlaps the volley)
    #pragma unroll
    for (int f = tid; f < C_ * D_ / 4; f += 128) {
        int s = f >> 4;
        int cc = (f & 15) * 4;
        quant_store4(Q16, s * SB_ + cc,
                     *(const float4*)(qbase + (size_t)s * ROWSTRIDE + cc));
    }
    cp_wait0();
    __syncthreads();

    int wid = tid >> 5;
    int t0 = wid * 16;

    // ---- Phase 1: scores S[t][s] = sum_e Q[t][e] K[s][e]   (16 mma)
    FragAcc acc[4];
    #pragma unroll
    for (int j = 0; j < 4; j++) wmma::fill_fragment(acc[j], 0.f);
    #pragma unroll
    for (int kk = 0; kk < 4; kk++) {
        int e0 = kk * 16;
        FragAR aq;
        wmma::load_matrix_sync(aq, &Q16[t0 * SB_ + e0], SB_);
        #pragma unroll
        for (int j = 0; j < 4; j++) {
            FragBC bk;
            wmma::load_matrix_sync(bk, &K16[(j * 16) * SB_ + e0], SB_); // B(e,s)=K[s][e]
            wmma::mma_sync(acc[j], aq, bk, acc[j]);
        }
    }
    #pragma unroll
    for (int j = 0; j < 4; j++)
        wmma::store_matrix_sync(&Sraw[t0 * SB_ + j * 16], acc[j], SB_, wmma::mem_row_major);
    __syncthreads();

    // ---- Causal mask (s <= t): fp32 reads to regs, sync, fp16 writes in place
    float r[32];
    #pragma unroll
    for (int i = 0; i < 32; i++) {
        int f = tid + i * 128;
        int t = f >> 6, s = f & 63;
        r[i] = Sraw[t * SB_ + s];
    }
    __syncthreads();
    #pragma unroll
    for (int i = 0; i < 32; i++) {
        int f = tid + i * 128;
        int t = f >> 6, s = f & 63;
        float x = (s <= t) ? r[i] : 0.f;
        Shi[t * SB_ + s] = __float2half_rn(x);
    }
    __syncthreads();

    // ---- Phase 2: Y = Q M^T + A V   (32 mma)
    #pragma unroll
    for (int j = 0; j < 4; j++) wmma::fill_fragment(acc[j], 0.f);
    #pragma unroll
    for (int kk = 0; kk < 4; kk++) {
        int e0 = kk * 16;
        FragAR aq;
        wmma::load_matrix_sync(aq, &Q16[t0 * SB_ + e0], SB_);
        #pragma unroll
        for (int j = 0; j < 4; j++) {
            FragBC bm;
            wmma::load_matrix_sync(bm, &M16[(j * 16) * SB_ + e0], SB_); // B(e,d)=M[d][e]
            wmma::mma_sync(acc[j], aq, bm, acc[j]);
        }
    }
    #pragma unroll
    for (int kk = 0; kk < 4; kk++) {
        int s0 = kk * 16;
        FragAR aa;
        wmma::load_matrix_sync(aa, &Shi[t0 * SB_ + s0], SB_);
        #pragma unroll
        for (int j = 0; j < 4; j++) {
            FragBR bv;
            wmma::load_matrix_sync(bv, &V16[s0 * SB_ + j * 16], SB_);  // B(s,d)=V[s][d]
            wmma::mma_sync(acc[j], aa, bv, acc[j]);
        }
    }

    float* ybase = y + (((size_t)b * T_ + (size_t)c * C_) * H_ + h) * D_;
    #pragma unroll
    for (int j = 0; j < 4; j++)
        wmma::store_matrix_sync(ybase + (size_t)t0 * ROWSTRIDE + j * 16, acc[j],
                                ROWSTRIDE, wmma::mem_row_major);
}

// ---------------------------------------------------------------------------
extern "C" void kernel_launch(void* const* d_in, const int* in_sizes, int n_in,
                              void* d_out, int out_size) {
    (void)in_sizes; (void)n_in; (void)out_size;
    const float* q = (const float*)d_in[0];
    const float* k = (const float*)d_in[1];
    const float* v = (const float*)d_in[2];
    float* y = (float*)d_out;

    cudaFuncSetAttribute(output_kernel, cudaFuncAttributeMaxDynamicSharedMemorySize,
                         SMEM3_BYTES);

    chunk_sum_kernel<<<BH_ * NC_, 128, SMEM1_BYTES>>>(k, v);
    prefix_kernel<<<(BH_ * 4096) / 256, 256>>>();
    output_kernel<<<BH_ * NC_, 128, SMEM3_BYTES>>>(q, y);
}

// round 14
// speedup vs baseline: 1.1629x; 1.1629x over previous
#include <cuda_runtime.h>
#include <cuda_fp16.h>
#include <mma.h>

using namespace nvcuda;

// Problem constants
#define B_  2
#define T_  4096
#define H_  8
#define D_  64
#define C_  64
#define NC_ (T_/C_)            // 64
#define BH_ (B_*H_)            // 16
#define ROWSTRIDE 512          // H_*D_
#define SB_ 72                 // fp16 smem row stride (LDSM conflict-free)
#define HB_ (C_ * SB_)         // 4608 halves = 9216 bytes per buffer
#define SRW_ 68                // fp32 pack-staging stride

// Scratch: fp16 chunk sums and fp16 exclusive-prefix state. 8MB each, L2-resident.
__device__ __half g_Sh[(size_t)BH_ * NC_ * D_ * D_];
__device__ __half g_M [(size_t)BH_ * NC_ * D_ * D_];

typedef wmma::fragment<wmma::matrix_a, 16, 16, 16, __half, wmma::row_major> FragAR;
typedef wmma::fragment<wmma::matrix_a, 16, 16, 16, __half, wmma::col_major> FragAC;
typedef wmma::fragment<wmma::matrix_b, 16, 16, 16, __half, wmma::row_major> FragBR;
typedef wmma::fragment<wmma::matrix_b, 16, 16, 16, __half, wmma::col_major> FragBC;
typedef wmma::fragment<wmma::accumulator, 16, 16, 16, float> FragAcc;

// Quantize 4 fp32 to fp16 and store (8B store).
__device__ __forceinline__ void quant_store4(__half* Bq, int idx, float4 x) {
    __half2 h01 = __floats2half2_rn(x.x, x.y);
    __half2 h23 = __floats2half2_rn(x.z, x.w);
    uint2 hh;
    hh.x = *(unsigned*)&h01; hh.y = *(unsigned*)&h23;
    *(uint2*)&Bq[idx] = hh;
}

__device__ __forceinline__ void cp_async16(void* sdst, const void* gsrc) {
    unsigned s = (unsigned)__cvta_generic_to_shared(sdst);
    asm volatile("cp.async.cg.shared.global [%0], [%1], 16;" :: "r"(s), "l"(gsrc));
}
__device__ __forceinline__ void cp_commit() { asm volatile("cp.async.commit_group;"); }
__device__ __forceinline__ void cp_wait0()  { asm volatile("cp.async.wait_group 0;" ::: "memory"); }

// ---------------------------------------------------------------------------
// Pass 1: S[d][e] = sum_s V[s][d] * K[s][e] per (bh, chunk); S written fp16.
// Disjoint fp32 pack-staging (no alias hazard -> one fewer sync).
// Recipe: LDG+quant -> sync -> 16 mma -> store -> sync -> pack STG.
// ---------------------------------------------------------------------------
#define SMEM1_BYTES (2 * HB_ * 2 + D_ * SRW_ * 4)   // 18432 + 17408 = 35840

__global__ void __launch_bounds__(128) chunk_sum_kernel(const float* __restrict__ k,
                                                        const float* __restrict__ v) {
    extern __shared__ __align__(16) char smraw1[];
    __half* K16 = (__half*)smraw1;
    __half* V16 = K16 + HB_;
    float*  Sraw = (float*)(V16 + HB_);   // [64][68] fp32, DISJOINT

    int blk = blockIdx.x;             // [0, 1024)
    int bh  = blk >> 6;
    int c   = blk & (NC_ - 1);
    int b   = bh >> 3, h = bh & 7;
    int tid = threadIdx.x;

    const float* kbase = k + (((size_t)b * T_ + (size_t)c * C_) * H_ + h) * D_;
    const float* vbase = v + (((size_t)b * T_ + (size_t)c * C_) * H_ + h) * D_;

    #pragma unroll
    for (int f = tid; f < C_ * D_ / 4; f += 128) {
        int s = f >> 4;
        int cc = (f & 15) * 4;
        quant_store4(K16, s * SB_ + cc,
                     *(const float4*)(kbase + (size_t)s * ROWSTRIDE + cc));
        quant_store4(V16, s * SB_ + cc,
                     *(const float4*)(vbase + (size_t)s * ROWSTRIDE + cc));
    }
    __syncthreads();

    int wid = tid >> 5;
    int d0 = wid * 16;

    FragAcc acc[4];
    #pragma unroll
    for (int j = 0; j < 4; j++) wmma::fill_fragment(acc[j], 0.f);

    #pragma unroll
    for (int kk = 0; kk < 4; kk++) {
        int s0 = kk * 16;
        FragAC av;
        wmma::load_matrix_sync(av, &V16[s0 * SB_ + d0], SB_);    // A(d,s)=V[s][d]
        #pragma unroll
        for (int j = 0; j < 4; j++) {
            FragBR bq;
            wmma::load_matrix_sync(bq, &K16[s0 * SB_ + j * 16], SB_); // B(s,e)=K[s][e]
            wmma::mma_sync(acc[j], av, bq, acc[j]);
        }
    }

    // Store straight to disjoint staging (no pre-store sync needed)
    #pragma unroll
    for (int j = 0; j < 4; j++)
        wmma::store_matrix_sync(&Sraw[d0 * SRW_ + j * 16], acc[j], SRW_, wmma::mem_row_major);
    __syncthreads();

    __half* Sout = g_Sh + (size_t)blk * (D_ * D_);
    #pragma unroll
    for (int f = tid; f < D_ * D_ / 4; f += 128) {
        int r = f >> 4;
        int cc = (f & 15) * 4;
        quant_store4(Sout, f * 4, *(const float4*)&Sraw[r * SRW_ + cc]);
    }
}

// ---------------------------------------------------------------------------
// Pass 2: exclusive prefix over the chunk axis; fp16 in (S), fp16 out (M).
// ---------------------------------------------------------------------------
__global__ void __launch_bounds__(256) prefix_kernel() {
    int gidx = blockIdx.x * 256 + threadIdx.x;   // [0, BH_*2048)
    int bh   = gidx >> 11;
    int pidx = gidx & 2047;
    const __half2* src = (const __half2*)g_Sh + (size_t)bh * NC_ * 2048 + pidx;
    __half2*       dst = (__half2*)g_M  + (size_t)bh * NC_ * 2048 + pidx;

    __half2 vals[NC_];
    #pragma unroll
    for (int c = 0; c < NC_; c++) vals[c] = src[(size_t)c * 2048];
    float rx = 0.f, ry = 0.f;
    #pragma unroll
    for (int c = 0; c < NC_; c++) {
        float2 t = __half22float2(vals[c]);
        dst[(size_t)c * 2048] = __floats2half2_rn(rx, ry);
        rx += t.x; ry += t.y;
    }
}

// ---------------------------------------------------------------------------
// Pass 3: Y = tril(Q K^T) V + Q M_prev^T per (bh, chunk).
// Reordered: QK mma -> score store -> QM mma (covers store->sync latency)
// -> sync -> mask into the dead K16 buffer (no alias, no reg staging)
// -> sync -> AV mma. 3 syncs total. smem 55.3KB -> 4 CTAs/SM.
// ---------------------------------------------------------------------------
#define SMEM3_BYTES (4 * HB_ * 2 + HB_ * 4)   // 36864 + 18432 = 55296

__global__ void __launch_bounds__(128) output_kernel(const float* __restrict__ q,
                                                     const float* __restrict__ k,
                                                     const float* __restrict__ v,
                                                     float* __restrict__ y) {
    extern __shared__ __align__(16) char smraw[];
    __half* Q16 = (__half*)smraw;
    __half* K16 = Q16 + HB_;
    __half* V16 = K16 + HB_;
    __half* M16 = V16 + HB_;
    float*  Sraw = (float*)(M16 + HB_);   // fp32 [64][72] (18432B, disjoint)
    __half* A16  = K16;                   // masked scores reuse the dead K16

    int blk = blockIdx.x;             // [0, 1024)
    int bh  = blk >> 6;
    int c   = blk & (NC_ - 1);
    int b   = bh >> 3, h = bh & 7;
    int tid = threadIdx.x;

    const float* qbase = q + (((size_t)b * T_ + (size_t)c * C_) * H_ + h) * D_;
    const float* kbase = k + (((size_t)b * T_ + (size_t)c * C_) * H_ + h) * D_;
    const float* vbase = v + (((size_t)b * T_ + (size_t)c * C_) * H_ + h) * D_;
    const __half* Mg = g_M + (size_t)blk * (D_ * D_);

    // Fire the M prefetch immediately (fp16, L2-resident)
    #pragma unroll
    for (int f = tid; f < D_ * D_ / 8; f += 128) {
        int d = f >> 3;
        int c8 = (f & 7) * 8;
        cp_async16(&M16[d * SB_ + c8], Mg + d * D_ + c8);
    }
    cp_commit();

    // Q/K/V: LDG fp32 + quantize (overlaps the M volley)
    #pragma unroll
    for (int f = tid; f < C_ * D_ / 4; f += 128) {
        int s = f >> 4;
        int cc = (f & 15) * 4;
        quant_store4(Q16, s * SB_ + cc,
                     *(const float4*)(qbase + (size_t)s * ROWSTRIDE + cc));
        quant_store4(K16, s * SB_ + cc,
                     *(const float4*)(kbase + (size_t)s * ROWSTRIDE + cc));
        quant_store4(V16, s * SB_ + cc,
                     *(const float4*)(vbase + (size_t)s * ROWSTRIDE + cc));
    }
    cp_wait0();
    __syncthreads();

    int wid = tid >> 5;
    int t0 = wid * 16;

    // ---- Phase 1: scores S[t][s] = sum_e Q[t][e] K[s][e]   (16 mma)
    FragAcc acc[4];
    #pragma unroll
    for (int j = 0; j < 4; j++) wmma::fill_fragment(acc[j], 0.f);
    #pragma unroll
    for (int kk = 0; kk < 4; kk++) {
        int e0 = kk * 16;
        FragAR aq;
        wmma::load_matrix_sync(aq, &Q16[t0 * SB_ + e0], SB_);
        #pragma unroll
        for (int j = 0; j < 4; j++) {
            FragBC bk;
            wmma::load_matrix_sync(bk, &K16[(j * 16) * SB_ + e0], SB_); // B(e,s)=K[s][e]
            wmma::mma_sync(acc[j], aq, bk, acc[j]);
        }
    }
    #pragma unroll
    for (int j = 0; j < 4; j++)
        wmma::store_matrix_sync(&Sraw[t0 * SB_ + j * 16], acc[j], SB_, wmma::mem_row_major);

    // ---- Phase 2a: Y += Q M^T (independent of scores; covers store latency)
    FragAcc accY[4];
    #pragma unroll
    for (int j = 0; j < 4; j++) wmma::fill_fragment(accY[j], 0.f);
    #pragma unroll
    for (int kk = 0; kk < 4; kk++) {
        int e0 = kk * 16;
        FragAR aq;
        wmma::load_matrix_sync(aq, &Q16[t0 * SB_ + e0], SB_);
        #pragma unroll
        for (int j = 0; j < 4; j++) {
            FragBC bm;
            wmma::load_matrix_sync(bm, &M16[(j * 16) * SB_ + e0], SB_); // B(e,d)=M[d][e]
            wmma::mma_sync(accY[j], aq, bm, accY[j]);
        }
    }
    __syncthreads();   // scores visible to all warps; K16 fully consumed

    // ---- Causal mask (s <= t): fp32 Sraw -> fp16 A16 (dead K16 region)
    #pragma unroll
    for (int i = 0; i < 32; i++) {
        int f = tid + i * 128;
        int t = f >> 6, s = f & 63;
        float x = (s <= t) ? Sraw[t * SB_ + s] : 0.f;
        A16[t * SB_ + s] = __float2half_rn(x);
    }
    __syncthreads();

    // ---- Phase 2b: Y += A V   (16 mma)
    #pragma unroll
    for (int kk = 0; kk < 4; kk++) {
        int s0 = kk * 16;
        FragAR aa;
        wmma::load_matrix_sync(aa, &A16[t0 * SB_ + s0], SB_);
        #pragma unroll
        for (int j = 0; j < 4; j++) {
            FragBR bv;
            wmma::load_matrix_sync(bv, &V16[s0 * SB_ + j * 16], SB_);  // B(s,d)=V[s][d]
            wmma::mma_sync(accY[j], aa, bv, accY[j]);
        }
    }

    float* ybase = y + (((size_t)b * T_ + (size_t)c * C_) * H_ + h) * D_;
    #pragma unroll
    for (int j = 0; j < 4; j++)
        wmma::store_matrix_sync(ybase + (size_t)t0 * ROWSTRIDE + j * 16, accY[j],
                                ROWSTRIDE, wmma::mem_row_major);
}

// ---------------------------------------------------------------------------
extern "C" void kernel_launch(void* const* d_in, const int* in_sizes, int n_in,
                              void* d_out, int out_size) {
    (void)in_sizes; (void)n_in; (void)out_size;
    const float* q = (const float*)d_in[0];
    const float* k = (const float*)d_in[1];
    const float* v = (const float*)d_in[2];
    float* y = (float*)d_out;

    cudaFuncSetAttribute(chunk_sum_kernel, cudaFuncAttributeMaxDynamicSharedMemorySize,
                         SMEM1_BYTES);
    cudaFuncSetAttribute(output_kernel, cudaFuncAttributeMaxDynamicSharedMemorySize,
                         SMEM3_BYTES);

    chunk_sum_kernel<<<BH_ * NC_, 128, SMEM1_BYTES>>>(k, v);
    prefix_kernel<<<(BH_ * 2048) / 256, 256>>>();
    output_kernel<<<BH_ * NC_, 128, SMEM3_BYTES>>>(q, k, v, y);
}